// round 13
// baseline (speedup 1.0000x reference)
#include <cuda_runtime.h>
#include <cstdint>

// NNUE HalfKP forward — SINGLE fused kernel, dataflow-triggered epilogue.
//   grid (64 kings x 20 row-slices of 32). Per block: stage 32 table rows
//   int32->int16 SMEM; bucket (sample,side) pairs by king; 8 warps x 4 pairs
//   dense-row predicated vadd2 accumulate (packed int16) -> g_part; after each
//   pair store: fence + per-sample atomic counter. The warp completing the
//   40th store (2 sides x 20 slices) runs that sample's FC epilogue inline:
//   combine partials + king bias rows + input_bias (mod 2^16 == astype(int16)),
//   clip, FC1/FC2 (packed-transposed weights, prepped by block(0,0) under a
//   ready-flag), output dot, atomicAdd. Last sample writes float output and
//   self-resets all counters (replay-safe).
//
// Inputs (ALL integers widened to int32 by the harness):
//  0 piece_positions (B,640)  1 king_positions (B,2)  2 input_weights (64,641,256)
//  3 input_bias (256)  4 w1 (32,512)  5 b1 (32)  6 w2 (32,32)  7 b2 (32)
//  8 out_w (32)  9 out_b (1)        out: float32 (1)

#define NQ    20                 // row slices
#define QR    32                 // rows per slice
#define MAXP  2048               // max (sample,side) pairs
#define MAXS  1024               // max samples
#define BCAP  128                // per-king bucket capacity (mean 32, sd 5.6)
#define TARGET (2 * NQ)          // partial stores per sample

__device__ uint4    g_part[NQ][MAXP * 32];   // packed-int16 partial sums (20 MB)
__device__ unsigned g_w1t[128 * 32];         // dp4a-packed w1, j-major [j*32+out]
__device__ int      g_w2t[32 * 32];          // w2 transposed [in*32+out]
__device__ int      g_scnt[MAXS];            // per-sample store counters (self-reset)
__device__ int      g_total;                 // scalar accumulator (self-reset)
__device__ int      g_done;                  // finished samples (self-reset)
__device__ int      g_wready;                // weights packed flag (sticky)

// ---- per-sample FC epilogue (whole warp) ----
__device__ __forceinline__ void run_fc(
    int s, int lane, int warp,
    const int* __restrict__ W32, const int* __restrict__ kings,
    const int* __restrict__ bias, const int* __restrict__ b1,
    const int* __restrict__ b2,  const int* __restrict__ ow,
    const int* __restrict__ ob,  float* __restrict__ out, int B,
    unsigned (*s_x)[64], int (*s_x1)[32])
{
    while (atomicAdd(&g_wready, 0) == 0) __nanosleep(100);  // bounded: block(0,0) sets it
    __threadfence();                                        // acquire partials

    // combine 20 slices x 2 sides (packed int16, mod 2^16 exact), MLP 4/step
    unsigned a0 = 0, a1 = 0, a2 = 0, a3 = 0;
    #pragma unroll
    for (int q = 0; q < NQ; q += 2) {
        const uint4 r0 = g_part[q][(2 * s + 0) * 32 + lane];
        const uint4 r1 = g_part[q][(2 * s + 1) * 32 + lane];
        const uint4 r2 = g_part[q + 1][(2 * s + 0) * 32 + lane];
        const uint4 r3 = g_part[q + 1][(2 * s + 1) * 32 + lane];
        a0 = __vadd2(__vadd2(__vadd2(a0, r0.x), r1.x), __vadd2(r2.x, r3.x));
        a1 = __vadd2(__vadd2(__vadd2(a1, r0.y), r1.y), __vadd2(r2.y, r3.y));
        a2 = __vadd2(__vadd2(__vadd2(a2, r0.z), r1.z), __vadd2(r2.z, r3.z));
        a3 = __vadd2(__vadd2(__vadd2(a3, r0.w), r1.w), __vadd2(r2.w, r3.w));
    }
    // per-king bias rows (row 640) + input_bias
    const int k0 = kings[2 * s + 0];
    const int k1 = kings[2 * s + 1];
    const int4* br0 = (const int4*)(W32 + ((size_t)k0 * 641 + 640) * 256 + lane * 8);
    const int4* br1 = (const int4*)(W32 + ((size_t)k1 * 641 + 640) * 256 + lane * 8);
    const int4 u0 = br0[0], v0 = br0[1];
    const int4 u1 = br1[0], v1 = br1[1];
    const int4 bA = ((const int4*)bias)[lane * 2 + 0];
    const int4 bB = ((const int4*)bias)[lane * 2 + 1];
    a0 = __vadd2(a0, (unsigned)(u0.x & 0xffff) | ((unsigned)u0.y << 16));
    a1 = __vadd2(a1, (unsigned)(u0.z & 0xffff) | ((unsigned)u0.w << 16));
    a2 = __vadd2(a2, (unsigned)(v0.x & 0xffff) | ((unsigned)v0.y << 16));
    a3 = __vadd2(a3, (unsigned)(v0.z & 0xffff) | ((unsigned)v0.w << 16));
    a0 = __vadd2(a0, (unsigned)(u1.x & 0xffff) | ((unsigned)u1.y << 16));
    a1 = __vadd2(a1, (unsigned)(u1.z & 0xffff) | ((unsigned)u1.w << 16));
    a2 = __vadd2(a2, (unsigned)(v1.x & 0xffff) | ((unsigned)v1.y << 16));
    a3 = __vadd2(a3, (unsigned)(v1.z & 0xffff) | ((unsigned)v1.w << 16));
    a0 = __vadd2(a0, (unsigned)(bA.x & 0xffff) | ((unsigned)bA.y << 16));
    a1 = __vadd2(a1, (unsigned)(bA.z & 0xffff) | ((unsigned)bA.w << 16));
    a2 = __vadd2(a2, (unsigned)(bB.x & 0xffff) | ((unsigned)bB.y << 16));
    a3 = __vadd2(a3, (unsigned)(bB.z & 0xffff) | ((unsigned)bB.w << 16));

    // clip int16 -> [0,127], pack 8 int8 into 2 words
    unsigned accs[4] = {a0, a1, a2, a3};
    int c8[8];
    #pragma unroll
    for (int kk = 0; kk < 4; kk++) {
        int lo = (int)(short)(accs[kk] & 0xffffu);
        int hi = (int)(short)(accs[kk] >> 16);
        c8[2 * kk + 0] = min(max(lo, 0), 127);
        c8[2 * kk + 1] = min(max(hi, 0), 127);
    }
    s_x[warp][lane * 2 + 0] = (unsigned)c8[0] | ((unsigned)c8[1] << 8) |
                              ((unsigned)c8[2] << 16) | ((unsigned)c8[3] << 24);
    s_x[warp][lane * 2 + 1] = (unsigned)c8[4] | ((unsigned)c8[5] << 8) |
                              ((unsigned)c8[6] << 16) | ((unsigned)c8[7] << 24);
    __syncwarp();

    // FC1: lane = output unit; x512 = [x, x]; 4 independent dp4a chains
    int v1a = b1[lane], v1b = 0, v1c = 0, v1d = 0;
    #pragma unroll 8
    for (int j = 0; j < 64; j += 2) {
        const int x0 = (int)s_x[warp][j];
        const int x1 = (int)s_x[warp][j + 1];
        v1a = __dp4a(x0, (int)__ldg(&g_w1t[j * 32 + lane]),        v1a);
        v1b = __dp4a(x0, (int)__ldg(&g_w1t[(64 + j) * 32 + lane]), v1b);
        v1c = __dp4a(x1, (int)__ldg(&g_w1t[(j + 1) * 32 + lane]),  v1c);
        v1d = __dp4a(x1, (int)__ldg(&g_w1t[(65 + j) * 32 + lane]), v1d);
    }
    int v1s = (v1a + v1b) + (v1c + v1d);
    v1s >>= 6;
    v1s = min(max(v1s, 0), 127);
    s_x1[warp][lane] = v1s;
    __syncwarp();

    // FC2
    int v2a = b2[lane], v2b = 0;
    #pragma unroll 8
    for (int o = 0; o < 32; o += 2) {
        v2a += s_x1[warp][o]     * __ldg(&g_w2t[o * 32 + lane]);
        v2b += s_x1[warp][o + 1] * __ldg(&g_w2t[(o + 1) * 32 + lane]);
    }
    int v2 = v2a + v2b;
    v2 >>= 6;
    v2 = min(max(v2, 0), 127);

    int contrib = v2 * ow[lane];
    #pragma unroll
    for (int sh = 16; sh; sh >>= 1)
        contrib += __shfl_xor_sync(0xffffffffu, contrib, sh);

    if (lane == 0) {
        atomicAdd(&g_total, contrib);
        __threadfence();
        const int done = atomicAdd(&g_done, 1);
        if (done == B - 1) {                         // unique last sample
            const int tot = atomicAdd(&g_total, 0);
            out[0] = (float)((tot + ob[0]) >> 4);
            atomicExch(&g_total, 0);                 // self-reset for next replay
            atomicExch(&g_done, 0);
        }
    }
    __syncwarp();
}

// ---------------- fused kernel ----------------
__global__ void __launch_bounds__(256, 4) hx_fused(
    const int* __restrict__ W32,
    const int* __restrict__ pp,
    const int* __restrict__ kings,
    const int* __restrict__ w1,
    const int* __restrict__ w2,
    const int* __restrict__ bias,
    const int* __restrict__ b1,
    const int* __restrict__ b2,
    const int* __restrict__ ow,
    const int* __restrict__ ob,
    float* __restrict__ out,
    int B)
{
    __shared__ short    s_tile[QR * 256];   // 16 KB
    __shared__ int      s_bucket[BCAP];
    __shared__ int      s_cnt;
    __shared__ unsigned s_x[8][64];
    __shared__ int      s_x1[8][32];

    const int k = blockIdx.x;
    const int q = blockIdx.y;
    const int warp = threadIdx.x >> 5;
    const int lane = threadIdx.x & 31;

    if (k == 0 && q == 0) {
        // weight prep, then publish ready flag
        for (int t = threadIdx.x; t < 32 * 128; t += 256) {
            const int o = t >> 7, j = t & 127;
            const int* p = w1 + t * 4;
            g_w1t[j * 32 + o] =
                (unsigned)(p[0] & 0xff) | ((unsigned)(p[1] & 0xff) << 8) |
                ((unsigned)(p[2] & 0xff) << 16) | ((unsigned)p[3] << 24);
        }
        for (int t = threadIdx.x; t < 32 * 32; t += 256)
            g_w2t[(t & 31) * 32 + (t >> 5)] = w2[t];
        __syncthreads();
        __threadfence();
        if (threadIdx.x == 0) atomicExch(&g_wready, 1);
    }
    if (threadIdx.x == 0) s_cnt = 0;

    // 1) kings[] scan loads into registers (in flight during tile staging)
    const int P = 2 * B;
    int kv[8];
    int nk = 0;
    #pragma unroll
    for (int j = 0; j < 8; j++) {
        const int i = threadIdx.x + j * 256;
        if (i < P) { kv[nk] = kings[i]; nk++; }
    }

    // 2) stage + narrow tile: rows [q*32, q*32+32) int32 -> int16 SMEM
    {
        const int4* src = (const int4*)(W32 + ((size_t)k * 641 + (size_t)q * QR) * 256);
        short4* dst = (short4*)s_tile;
        #pragma unroll
        for (int i = threadIdx.x; i < QR * 256 / 4; i += 256) {
            const int4 v = src[i];
            dst[i] = make_short4((short)v.x, (short)v.y, (short)v.z, (short)v.w);
        }
    }

    // 3) bucket the scanned pairs
    __syncthreads();
    for (int j = 0; j < nk; j++)
        if (kv[j] == k) {
            const int slot = atomicAdd(&s_cnt, 1);
            if (slot < BCAP) s_bucket[slot] = threadIdx.x + j * 256;
        }
    __syncthreads();

    const int cnt = min(s_cnt, BCAP);
    const char* tb = (const char*)s_tile + lane * 16;   // lane covers 8 dims

    // 8 warps x 4 pairs each; strided if cnt > 32
    for (int gb = warp * 4; gb < cnt; gb += 32) {
        const int npair = min(4, cnt - gb);

        unsigned m[4];
        int pid[4];
        #pragma unroll
        for (int j = 0; j < 4; j++) {
            const bool valid = (j < npair);
            const int  p = s_bucket[valid ? (gb + j) : gb];
            pid[j] = p;
            const int* ppq = pp + (size_t)(p >> 1) * 640 + q * QR;
            const unsigned b = __ballot_sync(0xffffffffu, ppq[lane] != 0);
            m[j] = valid ? b : 0u;
        }

        unsigned acc[4][4];
        #pragma unroll
        for (int j = 0; j < 4; j++)
            acc[j][0] = acc[j][1] = acc[j][2] = acc[j][3] = 0u;

        #pragma unroll
        for (int r = 0; r < QR; r++) {
            const uint4 row = *(const uint4*)(tb + (r << 9));
            #pragma unroll
            for (int j = 0; j < 4; j++) {
                if (m[j] & (1u << r)) {
                    acc[j][0] = __vadd2(acc[j][0], row.x);
                    acc[j][1] = __vadd2(acc[j][1], row.y);
                    acc[j][2] = __vadd2(acc[j][2], row.z);
                    acc[j][3] = __vadd2(acc[j][3], row.w);
                }
            }
        }

        #pragma unroll
        for (int j = 0; j < 4; j++)
            if (j < npair)
                g_part[q][pid[j] * 32 + lane] =
                    make_uint4(acc[j][0], acc[j][1], acc[j][2], acc[j][3]);

        // publish stores, bump per-sample counters; 40th store runs the epilogue
        __threadfence();
        #pragma unroll
        for (int j = 0; j < 4; j++) {
            if (j < npair) {
                const int s = pid[j] >> 1;
                int old = 0;
                if (lane == 0) old = atomicAdd(&g_scnt[s], 1);
                old = __shfl_sync(0xffffffffu, old, 0);
                if (old == TARGET - 1) {
                    if (lane == 0) atomicSub(&g_scnt[s], TARGET);  // self-reset
                    run_fc(s, lane, warp, W32, kings, bias, b1, b2, ow, ob,
                           out, B, s_x, s_x1);
                }
            }
        }
    }
}

extern "C" void kernel_launch(void* const* d_in, const int* in_sizes, int n_in,
                              void* d_out, int out_size) {
    const int B = in_sizes[0] / 640;
    hx_fused<<<dim3(64, NQ), 256>>>(
        (const int*)d_in[2],
        (const int*)d_in[0],
        (const int*)d_in[1],
        (const int*)d_in[4],
        (const int*)d_in[6],
        (const int*)d_in[3],
        (const int*)d_in[5],
        (const int*)d_in[7],
        (const int*)d_in[8],
        (const int*)d_in[9],
        (float*)d_out,
        B);
}

// round 14
// speedup vs baseline: 2.5255x; 2.5255x over previous
#include <cuda_runtime.h>
#include <cstdint>

// NNUE HalfKP forward — king-grouped, 2-kernel formulation.
//   phaseA: grid (64 kings x 5 row-slices of 128). 64 KB dynamic-SMEM tile,
//           2 blocks/SM (~1.08 waves), 8 warps x 4 pairs. Dense 128-row loop:
//           one LDS.128 per row feeds 4 pairs via predicated vadd2 (packed
//           int16). Block (0,0) zeroes scalars + pre-packs FC weights.
//   phaseB: warp per sample; 10 partials + 2 king bias rows + input_bias
//           (mod 2^16 == ref astype(int16)), clip, FC1/FC2 from L1-resident
//           packed-transposed global weights, output dot, atomicAdd;
//           last block writes floor_div(total + out_b, 16) as float32.
//
// Inputs (ALL integers widened to int32 by the harness):
//  0 piece_positions (B,640)  1 king_positions (B,2)  2 input_weights (64,641,256)
//  3 input_bias (256)  4 w1 (32,512)  5 b1 (32)  6 w2 (32,32)  7 b2 (32)
//  8 out_w (32)  9 out_b (1)        out: float32 (1)

#define NQ    5                  // row slices
#define QR    128                // rows per slice
#define MW    4                  // mask words per slice (128/32)
#define MAXP  2048               // max (sample,side) pairs (B <= 1024)
#define BCAP  128                // per-king bucket capacity (mean 32, sd 5.6)
#define TILE_BYTES (QR * 512)    // 64 KB

__device__ uint4    g_part[NQ][MAXP * 32];   // packed-int16 partial sums (5 MB)
__device__ unsigned g_w1t[128 * 32];         // dp4a-packed w1, j-major [j*32+out]
__device__ int      g_w2t[32 * 32];          // w2 transposed [in*32+out]
__device__ int      g_total;
__device__ int      g_done;

// ---------------- phase A ----------------
__global__ void __launch_bounds__(256, 2) hx_phaseA(
    const int* __restrict__ W32,
    const int* __restrict__ pp,
    const int* __restrict__ kings,
    const int* __restrict__ w1,
    const int* __restrict__ w2,
    int B)
{
    extern __shared__ short s_tile[];     // [QR][256] int16, 64 KB
    __shared__ int s_bucket[BCAP];
    __shared__ int s_cnt;

    const int k = blockIdx.x;
    const int q = blockIdx.y;

    if (k == 0 && q == 0) {
        if (threadIdx.x == 0) { g_total = 0; g_done = 0; }
        for (int t = threadIdx.x; t < 32 * 128; t += 256) {
            const int o = t >> 7, j = t & 127;
            const int* p = w1 + t * 4;
            g_w1t[j * 32 + o] =
                (unsigned)(p[0] & 0xff) | ((unsigned)(p[1] & 0xff) << 8) |
                ((unsigned)(p[2] & 0xff) << 16) | ((unsigned)p[3] << 24);
        }
        for (int t = threadIdx.x; t < 32 * 32; t += 256)
            g_w2t[(t & 31) * 32 + (t >> 5)] = w2[t];
    }
    if (threadIdx.x == 0) s_cnt = 0;

    // 1) kings[] scan loads into registers (in flight during tile staging)
    const int P = 2 * B;
    int kv[8];
    int nk = 0;
    #pragma unroll
    for (int j = 0; j < 8; j++) {
        const int i = threadIdx.x + j * 256;
        if (i < P) { kv[nk] = kings[i]; nk++; }
    }

    // 2) stage + narrow tile: rows [q*128, q*128+128) int32 -> int16 SMEM
    {
        const int4* src = (const int4*)(W32 + ((size_t)k * 641 + (size_t)q * QR) * 256);
        short4* dst = (short4*)s_tile;
        #pragma unroll 8
        for (int i = threadIdx.x; i < QR * 256 / 4; i += 256) {
            const int4 v = src[i];
            dst[i] = make_short4((short)v.x, (short)v.y, (short)v.z, (short)v.w);
        }
    }

    // 3) bucket the scanned pairs
    __syncthreads();   // s_cnt visible
    for (int j = 0; j < nk; j++)
        if (kv[j] == k) {
            const int slot = atomicAdd(&s_cnt, 1);
            if (slot < BCAP) s_bucket[slot] = threadIdx.x + j * 256;
        }
    __syncthreads();

    const int cnt = min(s_cnt, BCAP);
    const int warp = threadIdx.x >> 5;
    const int lane = threadIdx.x & 31;
    const char* tb = (const char*)s_tile + lane * 16;   // lane covers 8 dims

    // 8 warps x 4 pairs each; strided if cnt > 32
    for (int gb = warp * 4; gb < cnt; gb += 32) {
        const int npair = min(4, cnt - gb);

        unsigned m[4][MW];    // [pair][word], fully register-resident
        int pid[4];
        #pragma unroll
        for (int j = 0; j < 4; j++) {
            const bool valid = (j < npair);
            const int  p = s_bucket[valid ? (gb + j) : gb];
            pid[j] = p;
            const int* ppq = pp + (size_t)(p >> 1) * 640 + q * QR;
            #pragma unroll
            for (int w = 0; w < MW; w++) {
                const unsigned b = __ballot_sync(0xffffffffu, ppq[w * 32 + lane] != 0);
                m[j][w] = valid ? b : 0u;
            }
        }

        unsigned acc[4][4];
        #pragma unroll
        for (int j = 0; j < 4; j++)
            acc[j][0] = acc[j][1] = acc[j][2] = acc[j][3] = 0u;

        #pragma unroll
        for (int w = 0; w < MW; w++) {
            const char* tbw = tb + ((w * 32) << 9);
            #pragma unroll 16
            for (int r = 0; r < 32; r++) {
                const uint4 row = *(const uint4*)(tbw + (r << 9));
                #pragma unroll
                for (int j = 0; j < 4; j++) {
                    if (m[j][w] & (1u << r)) {
                        acc[j][0] = __vadd2(acc[j][0], row.x);
                        acc[j][1] = __vadd2(acc[j][1], row.y);
                        acc[j][2] = __vadd2(acc[j][2], row.z);
                        acc[j][3] = __vadd2(acc[j][3], row.w);
                    }
                }
            }
        }

        #pragma unroll
        for (int j = 0; j < 4; j++)
            if (j < npair)
                g_part[q][pid[j] * 32 + lane] =
                    make_uint4(acc[j][0], acc[j][1], acc[j][2], acc[j][3]);
    }
}

// ---------------- phase B: combine + FC + finalize ----------------
__global__ void __launch_bounds__(256, 1) hx_phaseB(
    const int* __restrict__ W32,
    const int* __restrict__ kings,
    const int* __restrict__ bias,
    const int* __restrict__ b1,
    const int* __restrict__ b2,
    const int* __restrict__ ow,
    const int* __restrict__ ob,
    float* __restrict__ out,
    int B, int nblocks)
{
    __shared__ unsigned s_x[8][64];
    __shared__ int      s_x1[8][32];
    __shared__ int      s_wsum[8];

    const int warp = threadIdx.x >> 5;
    const int lane = threadIdx.x & 31;
    const int s = blockIdx.x * 8 + warp;
    int contrib = 0;

    if (s < B) {
        // ---- load ALL partials + bias rows first: ~16 loads in flight ----
        uint4 r[2 * NQ];
        #pragma unroll
        for (int q = 0; q < NQ; q++) {
            r[2 * q + 0] = g_part[q][(2 * s + 0) * 32 + lane];
            r[2 * q + 1] = g_part[q][(2 * s + 1) * 32 + lane];
        }
        const int k0 = kings[2 * s + 0];
        const int k1 = kings[2 * s + 1];
        const int4* br0 = (const int4*)(W32 + ((size_t)k0 * 641 + 640) * 256 + lane * 8);
        const int4* br1 = (const int4*)(W32 + ((size_t)k1 * 641 + 640) * 256 + lane * 8);
        const int4 u0 = br0[0], v0 = br0[1];
        const int4 u1 = br1[0], v1 = br1[1];
        const int4 bA = ((const int4*)bias)[lane * 2 + 0];
        const int4 bB = ((const int4*)bias)[lane * 2 + 1];

        // ---- reduce (packed int16, mod 2^16 exact) ----
        unsigned a0 = 0, a1 = 0, a2 = 0, a3 = 0;
        #pragma unroll
        for (int i = 0; i < 2 * NQ; i++) {
            a0 = __vadd2(a0, r[i].x); a1 = __vadd2(a1, r[i].y);
            a2 = __vadd2(a2, r[i].z); a3 = __vadd2(a3, r[i].w);
        }
        a0 = __vadd2(a0, (unsigned)(u0.x & 0xffff) | ((unsigned)u0.y << 16));
        a1 = __vadd2(a1, (unsigned)(u0.z & 0xffff) | ((unsigned)u0.w << 16));
        a2 = __vadd2(a2, (unsigned)(v0.x & 0xffff) | ((unsigned)v0.y << 16));
        a3 = __vadd2(a3, (unsigned)(v0.z & 0xffff) | ((unsigned)v0.w << 16));
        a0 = __vadd2(a0, (unsigned)(u1.x & 0xffff) | ((unsigned)u1.y << 16));
        a1 = __vadd2(a1, (unsigned)(u1.z & 0xffff) | ((unsigned)u1.w << 16));
        a2 = __vadd2(a2, (unsigned)(v1.x & 0xffff) | ((unsigned)v1.y << 16));
        a3 = __vadd2(a3, (unsigned)(v1.z & 0xffff) | ((unsigned)v1.w << 16));
        a0 = __vadd2(a0, (unsigned)(bA.x & 0xffff) | ((unsigned)bA.y << 16));
        a1 = __vadd2(a1, (unsigned)(bA.z & 0xffff) | ((unsigned)bA.w << 16));
        a2 = __vadd2(a2, (unsigned)(bB.x & 0xffff) | ((unsigned)bB.y << 16));
        a3 = __vadd2(a3, (unsigned)(bB.z & 0xffff) | ((unsigned)bB.w << 16));

        // clip int16 -> [0,127], pack 8 int8 into 2 words
        unsigned accs[4] = {a0, a1, a2, a3};
        int c8[8];
        #pragma unroll
        for (int kk = 0; kk < 4; kk++) {
            int lo = (int)(short)(accs[kk] & 0xffffu);
            int hi = (int)(short)(accs[kk] >> 16);
            c8[2 * kk + 0] = min(max(lo, 0), 127);
            c8[2 * kk + 1] = min(max(hi, 0), 127);
        }
        s_x[warp][lane * 2 + 0] = (unsigned)c8[0] | ((unsigned)c8[1] << 8) |
                                  ((unsigned)c8[2] << 16) | ((unsigned)c8[3] << 24);
        s_x[warp][lane * 2 + 1] = (unsigned)c8[4] | ((unsigned)c8[5] << 8) |
                                  ((unsigned)c8[6] << 16) | ((unsigned)c8[7] << 24);
        __syncwarp();

        // FC1: lane = output unit; x512 = [x, x]; 4 independent dp4a chains
        int v1a = b1[lane], v1b = 0, v1c = 0, v1d = 0;
        #pragma unroll 8
        for (int j = 0; j < 64; j += 2) {
            const int x0 = (int)s_x[warp][j];
            const int x1 = (int)s_x[warp][j + 1];
            v1a = __dp4a(x0, (int)__ldg(&g_w1t[j * 32 + lane]),        v1a);
            v1b = __dp4a(x0, (int)__ldg(&g_w1t[(64 + j) * 32 + lane]), v1b);
            v1c = __dp4a(x1, (int)__ldg(&g_w1t[(j + 1) * 32 + lane]),  v1c);
            v1d = __dp4a(x1, (int)__ldg(&g_w1t[(65 + j) * 32 + lane]), v1d);
        }
        int v1s = (v1a + v1b) + (v1c + v1d);
        v1s >>= 6;
        v1s = min(max(v1s, 0), 127);
        s_x1[warp][lane] = v1s;
        __syncwarp();

        // FC2 from transposed global (coalesced, L1-resident), 2 chains
        int v2a = b2[lane], v2b = 0;
        #pragma unroll 8
        for (int o = 0; o < 32; o += 2) {
            v2a += s_x1[warp][o]     * __ldg(&g_w2t[o * 32 + lane]);
            v2b += s_x1[warp][o + 1] * __ldg(&g_w2t[(o + 1) * 32 + lane]);
        }
        int v2 = v2a + v2b;
        v2 >>= 6;
        v2 = min(max(v2, 0), 127);

        contrib = v2 * ow[lane];
        #pragma unroll
        for (int sh = 16; sh; sh >>= 1)
            contrib += __shfl_xor_sync(0xffffffffu, contrib, sh);
    }

    if (lane == 0) s_wsum[warp] = contrib;
    __syncthreads();
    if (threadIdx.x == 0) {
        int t = 0;
        #pragma unroll
        for (int w = 0; w < 8; w++) t += s_wsum[w];
        atomicAdd(&g_total, t);
        __threadfence();
        if (atomicAdd(&g_done, 1) == nblocks - 1) {
            const int tot = atomicAdd(&g_total, 0);
            out[0] = (float)((tot + ob[0]) >> 4);
        }
    }
}

extern "C" void kernel_launch(void* const* d_in, const int* in_sizes, int n_in,
                              void* d_out, int out_size) {
    const int B = in_sizes[0] / 640;
    const int sblocks = (B + 7) / 8;

    static bool attr_set = false;
    if (!attr_set) {
        cudaFuncSetAttribute(hx_phaseA,
            cudaFuncAttributeMaxDynamicSharedMemorySize, TILE_BYTES);
        attr_set = true;
    }

    hx_phaseA<<<dim3(64, NQ), 256, TILE_BYTES>>>(
        (const int*)d_in[2], (const int*)d_in[0], (const int*)d_in[1],
        (const int*)d_in[4], (const int*)d_in[6], B);
    hx_phaseB<<<sblocks, 256>>>(
        (const int*)d_in[2],
        (const int*)d_in[1],
        (const int*)d_in[3],
        (const int*)d_in[5],
        (const int*)d_in[7],
        (const int*)d_in[8],
        (const int*)d_in[9],
        (float*)d_out,
        B, sblocks);
}